// round 10
// baseline (speedup 1.0000x reference)
#include <cuda_runtime.h>
#include <stdint.h>

#define BATCH 64
#define NPTS  131072
#define MPTS  2048
#define TILE  2048                 // points per block
#define NTILE (NPTS / TILE)        // 64 tiles per batch
#define NWORDS (NPTS / 32)         // 4096 mask words per batch
#define NCOARSE 512                // every 8th word prefix

// ---- scratch (device globals; zero-initialized; no runtime allocation) ----
__device__ __align__(16) unsigned g_maskbits[BATCH * NWORDS];   // 1 bit per point
__device__ __align__(16) int g_wordpref[BATCH * NWORDS];        // exclusive popc prefix per word
__device__ __align__(16) int g_coarse[BATCH * NCOARSE];         // prefix at every 8th word
__device__ float    g_blocksum[BATCH * NTILE * 3];              // per-tile masked xyz sums
__device__ __align__(16) float4 g_meancnt[BATCH];               // {mx,my,mz, cnt-as-float-bits}
__device__ __align__(8) uint2  g_rand[BATCH * MPTS];            // {hi, lo} threefry draws
__device__ int      g_arrive[BATCH];                            // per-batch arrival counters

// ---------------- Threefry-2x32 (matches JAX exactly) ----------------
__host__ __device__ inline void threefry2x32(uint32_t k0, uint32_t k1,
                                             uint32_t c0, uint32_t c1,
                                             uint32_t& o0, uint32_t& o1) {
    uint32_t ks2 = k0 ^ k1 ^ 0x1BD11BDAu;
    uint32_t x0 = c0 + k0, x1 = c1 + k1;
#define TF_ROUND(r) { x0 += x1; x1 = (x1 << (r)) | (x1 >> (32 - (r))); x1 ^= x0; }
    TF_ROUND(13) TF_ROUND(15) TF_ROUND(26) TF_ROUND(6)
    x0 += k1;  x1 += ks2 + 1u;
    TF_ROUND(17) TF_ROUND(29) TF_ROUND(16) TF_ROUND(24)
    x0 += ks2; x1 += k0 + 2u;
    TF_ROUND(13) TF_ROUND(15) TF_ROUND(26) TF_ROUND(6)
    x0 += k0;  x1 += k1 + 3u;
    TF_ROUND(17) TF_ROUND(29) TF_ROUND(16) TF_ROUND(24)
    x0 += k1;  x1 += ks2 + 4u;
    TF_ROUND(13) TF_ROUND(15) TF_ROUND(26) TF_ROUND(6)
    x0 += ks2; x1 += k0 + 5u;
#undef TF_ROUND
    o0 = x0; o1 = x1;
}

// ---------------- Kernel 1: mask + sums + threefry; last block per batch builds
//                  fine prefix + coarse prefix + meancnt ----------------
__global__ void __launch_bounds__(256)
k_mask_stats(const float* __restrict__ pc, const float* __restrict__ logits,
             uint32_t k1a, uint32_t k1b, uint32_t k2a, uint32_t k2b,
             float* __restrict__ out_mean, int has_mean) {
    const int tile = blockIdx.x;             // 0..NTILE-1
    const int b    = blockIdx.y;             // 0..BATCH-1
    const int t    = threadIdx.x;
    const int lane = t & 31, warp = t >> 5;

    const float*  l0 = logits + (size_t)b * 2 * NPTS;
    const float*  l1 = l0 + NPTS;
    const float4* p4 = (const float4*)pc + (size_t)b * NPTS;

    const int wbase = tile * TILE + warp * 256;   // this warp's 256 points
    float sx = 0.f, sy = 0.f, sz = 0.f;

    #pragma unroll
    for (int k = 0; k < 8; ++k) {
        const int n = wbase + k * 32 + lane;
        const bool m = __ldg(&l0[n]) < __ldg(&l1[n]);
        const unsigned bal = __ballot_sync(0xffffffffu, m);
        const float4 p = __ldg(&p4[n]);
        if (lane == 0)
            g_maskbits[(size_t)b * NWORDS + (unsigned)(wbase + k * 32) / 32] = bal;
        if (m) { sx += p.x; sy += p.y; sz += p.z; }
    }

    // free ALU under the memory shadow: threefry draws for selection
    if (warp == 0) {
        const uint32_t slot = (uint32_t)(b * MPTS + tile * 32 + lane);
        uint32_t h0, h1, q0, q1;
        threefry2x32(k1a, k1b, 0u, slot, h0, h1);
        threefry2x32(k2a, k2b, 0u, slot, q0, q1);
        g_rand[slot] = make_uint2(h0 ^ h1, q0 ^ q1);
    }

    #pragma unroll
    for (int o = 16; o; o >>= 1) {
        sx += __shfl_down_sync(0xffffffffu, sx, o);
        sy += __shfl_down_sync(0xffffffffu, sy, o);
        sz += __shfl_down_sync(0xffffffffu, sz, o);
    }
    __shared__ float ss[8][3];
    if (lane == 0) { ss[warp][0] = sx; ss[warp][1] = sy; ss[warp][2] = sz; }
    __syncthreads();
    if (warp == 0 && lane < 8) {
        sx = ss[lane][0]; sy = ss[lane][1]; sz = ss[lane][2];
        #pragma unroll
        for (int o = 4; o; o >>= 1) {
            sx += __shfl_down_sync(0x000000ffu, sx, o);
            sy += __shfl_down_sync(0x000000ffu, sy, o);
            sz += __shfl_down_sync(0x000000ffu, sz, o);
        }
        if (lane == 0) {
            const int idx = b * NTILE + tile;
            g_blocksum[idx * 3 + 0] = sx;
            g_blocksum[idx * 3 + 1] = sy;
            g_blocksum[idx * 3 + 2] = sz;
        }
    }
    __syncthreads();

    // ---- arrival protocol (threadfenceReduction pattern) ----
    __shared__ int s_islast;
    if (t == 0) {
        __threadfence();                      // publish this block's writes
        const int old = atomicAdd(&g_arrive[b], 1);
        s_islast = (old == NTILE - 1);
    }
    __syncthreads();
    if (!s_islast) return;
    if (t == 0) g_arrive[b] = 0;              // reset for next graph replay
    __threadfence();

    // ================= last block of batch b: prefixes + meancnt =================
    const uint4* mb4 = (const uint4*)(g_maskbits + (size_t)b * NWORDS);
    uint4 w4[4];
    #pragma unroll
    for (int i = 0; i < 4; ++i) w4[i] = mb4[t * 4 + i];

    int s = 0;
    #pragma unroll
    for (int i = 0; i < 4; ++i)
        s += __popc(w4[i].x) + __popc(w4[i].y) + __popc(w4[i].z) + __popc(w4[i].w);

    int inc = s;
    #pragma unroll
    for (int o = 1; o < 32; o <<= 1) {
        int v = __shfl_up_sync(0xffffffffu, inc, o);
        if (lane >= o) inc += v;
    }
    __shared__ int swarp[8], swpref[8], stot;
    if (lane == 31) swarp[warp] = inc;
    __syncthreads();
    if (warp == 0 && lane < 8) {
        int v = swarp[lane], winc = v;
        #pragma unroll
        for (int o = 1; o < 8; o <<= 1) {
            int u = __shfl_up_sync(0x000000ffu, winc, o);
            if (lane >= o) winc += u;
        }
        swpref[lane] = winc - v;
        if (lane == 7) stot = winc;
    }
    __syncthreads();

    {
        int run = swpref[warp] + (inc - s);   // exclusive prefix at word t*16
        const int c0 = run;
        int* __restrict__ pref = g_wordpref + (size_t)b * NWORDS + t * 16;
        int tmp[4];
        #pragma unroll
        for (int i = 0; i < 2; ++i) {         // words 0..7
            tmp[0] = run; run += __popc(w4[i].x);
            tmp[1] = run; run += __popc(w4[i].y);
            tmp[2] = run; run += __popc(w4[i].z);
            tmp[3] = run; run += __popc(w4[i].w);
            ((int4*)pref)[i] = make_int4(tmp[0], tmp[1], tmp[2], tmp[3]);
        }
        const int c1 = run;                   // prefix at word t*16 + 8
        #pragma unroll
        for (int i = 2; i < 4; ++i) {         // words 8..15
            tmp[0] = run; run += __popc(w4[i].x);
            tmp[1] = run; run += __popc(w4[i].y);
            tmp[2] = run; run += __popc(w4[i].z);
            tmp[3] = run; run += __popc(w4[i].w);
            ((int4*)pref)[i] = make_int4(tmp[0], tmp[1], tmp[2], tmp[3]);
        }
        ((int2*)(g_coarse + (size_t)b * NCOARSE))[t] = make_int2(c0, c1);
    }

    const int tot = stot;

    if (warp == 0) {                          // mean from 64 per-tile partials
        const int i0 = (b * NTILE + lane) * 3;
        const int i1 = (b * NTILE + lane + 32) * 3;
        float mx = g_blocksum[i0 + 0] + g_blocksum[i1 + 0];
        float my = g_blocksum[i0 + 1] + g_blocksum[i1 + 1];
        float mz = g_blocksum[i0 + 2] + g_blocksum[i1 + 2];
        #pragma unroll
        for (int o = 16; o; o >>= 1) {
            mx += __shfl_down_sync(0xffffffffu, mx, o);
            my += __shfl_down_sync(0xffffffffu, my, o);
            mz += __shfl_down_sync(0xffffffffu, mz, o);
        }
        if (lane == 0) {
            const float d = fmaxf((float)tot, 1.0f);
            mx /= d; my /= d; mz /= d;
            g_meancnt[b] = make_float4(mx, my, mz, __int_as_float(tot));
            if (has_mean) {
                out_mean[b * 3 + 0] = mx;
                out_mean[b * 3 + 1] = my;
                out_mean[b * 3 + 2] = mz;
            }
        }
    }
}

// ---------------- Kernel 2: selection, shortened dependent chain ----------------
__global__ void __launch_bounds__(256)
k_select(const float* __restrict__ pc, float* __restrict__ out) {
    const int b = blockIdx.y;
    const int t = threadIdx.x;
    const int j = blockIdx.x * 256 + t;       // 0..MPTS-1
    const int slot = b * MPTS + j;

    __shared__ int s_coarse[NCOARSE];          // 2 KB
    ((int2*)s_coarse)[t] = __ldg(&((const int2*)(g_coarse + (size_t)b * NCOARSE))[t]);

    // packed metadata: 2 loads total, issued in parallel
    const float4 mc  = __ldg(&g_meancnt[b]);
    const uint2  rnd2 = __ldg(&g_rand[slot]);
    const int cnt = __float_as_int(mc.w);

    __syncthreads();

    float* __restrict__ o = out + (size_t)slot * 3;

    if (cnt == 0) {                           // empty-mask override: batch id
        const float v = (float)b;
        o[0] = v; o[1] = v; o[2] = v;
        return;
    }

    const uint32_t span = (uint32_t)cnt;
    uint32_t mult = 65536u % span;
    mult = (mult * mult) % span;              // uint32 wraparound — matches lax semantics
    const int rnd = (int)(((rnd2.x % span) * mult + (rnd2.y % span)) % span);
    const int sel = (cnt <= MPTS && j < cnt) ? j : rnd;

    // 9-step binary search in smem coarse: largest c with coarse[c] <= sel
    int lo = 0, hi = NCOARSE;
    #pragma unroll
    for (int st = 0; st < 9; ++st) {          // 2^9 = 512
        const int mid = (lo + hi) >> 1;
        const bool le = (s_coarse[mid] <= sel);
        lo = le ? mid : lo;
        hi = le ? hi  : mid;
    }

    // fine window: 8 prefixes AND 8 words fetched in parallel (independent loads)
    const int4*  pf = (const int4*) (g_wordpref + (size_t)b * NWORDS + lo * 8);
    const uint4* wf = (const uint4*)(g_maskbits + (size_t)b * NWORDS + lo * 8);
    const int4  pA = __ldg(&pf[0]);
    const int4  pB = __ldg(&pf[1]);
    const uint4 wA = __ldg(&wf[0]);
    const uint4 wB = __ldg(&wf[1]);

    const int k = (pA.y <= sel) + (pA.z <= sel) + (pA.w <= sel)
                + (pB.x <= sel) + (pB.y <= sel) + (pB.z <= sel) + (pB.w <= sel);
    int plo = pA.x;
    plo = (k >= 1) ? pA.y : plo;  plo = (k >= 2) ? pA.z : plo;
    plo = (k >= 3) ? pA.w : plo;  plo = (k >= 4) ? pB.x : plo;
    plo = (k >= 5) ? pB.y : plo;  plo = (k >= 6) ? pB.z : plo;
    plo = (k >= 7) ? pB.w : plo;
    unsigned w = wA.x;
    w = (k >= 1) ? wA.y : w;  w = (k >= 2) ? wA.z : w;
    w = (k >= 3) ? wA.w : w;  w = (k >= 4) ? wB.x : w;
    w = (k >= 5) ? wB.y : w;  w = (k >= 6) ? wB.z : w;
    w = (k >= 7) ? wB.w : w;
    const int word = lo * 8 + k;

    int r = sel - plo;                        // r-th set bit of w (0-based)
    int p = 0;
    {
        int cc = __popc(w & 0xFFFFu); if (r >= cc) { r -= cc; p += 16; w >>= 16; }
        cc = __popc(w & 0xFFu);       if (r >= cc) { r -= cc; p += 8;  w >>= 8;  }
        cc = __popc(w & 0xFu);        if (r >= cc) { r -= cc; p += 4;  w >>= 4;  }
        cc = __popc(w & 0x3u);        if (r >= cc) { r -= cc; p += 2;  w >>= 2;  }
        cc = (int)(w & 1u);           if (r >= cc) {          p += 1;            }
    }
    const int idx = word * 32 + p;

    const float4 pt = __ldg((const float4*)pc + (size_t)b * NPTS + idx);
    o[0] = pt.x - mc.x;
    o[1] = pt.y - mc.y;
    o[2] = pt.z - mc.z;
}

// ---------------- launch ----------------
extern "C" void kernel_launch(void* const* d_in, const int* in_sizes, int n_in,
                              void* d_out, int out_size) {
    const float* pc     = (const float*)d_in[0];
    const float* logits = (const float*)d_in[1];
    if (n_in >= 2 && in_sizes[0] == BATCH * 2 * NPTS && in_sizes[1] == BATCH * NPTS * 4) {
        pc     = (const float*)d_in[1];
        logits = (const float*)d_in[0];
    }
    float* out = (float*)d_out;

    // split(key(42)) — partitionable/foldlike: counters (0,0) and (0,1)
    uint32_t k1a, k1b, k2a, k2b;
    threefry2x32(0u, 42u, 0u, 0u, k1a, k1b);
    threefry2x32(0u, 42u, 0u, 1u, k2a, k2b);

    const size_t obj_elems = (size_t)BATCH * MPTS * 3;
    const int has_mean = (out_size >= (int)(obj_elems + BATCH * 3)) ? 1 : 0;

    k_mask_stats<<<dim3(NTILE, BATCH), 256>>>(pc, logits, k1a, k1b, k2a, k2b,
                                              out + obj_elems, has_mean);
    k_select    <<<dim3(MPTS / 256, BATCH), 256>>>(pc, out);
}

// round 11
// speedup vs baseline: 1.0537x; 1.0537x over previous
#include <cuda_runtime.h>
#include <stdint.h>

#define BATCH 64
#define NPTS  131072
#define MPTS  2048
#define TILE  2048                 // points per mask block
#define NTILE (NPTS / TILE)        // 64 tiles per batch
#define NWORDS (NPTS / 32)         // 4096 mask words per batch
#define NCOARSE 512                // every 8th word prefix
#define NMASKBLK (BATCH * NTILE)   // 4096
#define NSELBLK  (BATCH * 8)       // 512 (8 select blocks per batch)

// ---- scratch (device globals; zero-initialized; no runtime allocation) ----
__device__ __align__(16) unsigned g_maskbits[BATCH * NWORDS];
__device__ __align__(16) int g_wordpref[BATCH * NWORDS];
__device__ __align__(16) int g_coarse[BATCH * NCOARSE];
__device__ float    g_blocksum[BATCH * NTILE * 3];
__device__ __align__(16) float4 g_meancnt[BATCH];               // {mx,my,mz, cnt-bits}
__device__ __align__(8) uint2  g_rand[BATCH * MPTS];            // {hi, lo} threefry draws
__device__ int      g_arrive[BATCH];                            // mask arrival counters
__device__ int      g_ready[BATCH];                             // per-batch release flags
__device__ int      g_seldone[BATCH];                           // select-block completion

// ---------------- Threefry-2x32 (matches JAX exactly) ----------------
__host__ __device__ inline void threefry2x32(uint32_t k0, uint32_t k1,
                                             uint32_t c0, uint32_t c1,
                                             uint32_t& o0, uint32_t& o1) {
    uint32_t ks2 = k0 ^ k1 ^ 0x1BD11BDAu;
    uint32_t x0 = c0 + k0, x1 = c1 + k1;
#define TF_ROUND(r) { x0 += x1; x1 = (x1 << (r)) | (x1 >> (32 - (r))); x1 ^= x0; }
    TF_ROUND(13) TF_ROUND(15) TF_ROUND(26) TF_ROUND(6)
    x0 += k1;  x1 += ks2 + 1u;
    TF_ROUND(17) TF_ROUND(29) TF_ROUND(16) TF_ROUND(24)
    x0 += ks2; x1 += k0 + 2u;
    TF_ROUND(13) TF_ROUND(15) TF_ROUND(26) TF_ROUND(6)
    x0 += k0;  x1 += k1 + 3u;
    TF_ROUND(17) TF_ROUND(29) TF_ROUND(16) TF_ROUND(24)
    x0 += k1;  x1 += ks2 + 4u;
    TF_ROUND(13) TF_ROUND(15) TF_ROUND(26) TF_ROUND(6)
    x0 += ks2; x1 += k0 + 5u;
#undef TF_ROUND
    o0 = x0; o1 = x1;
}

// ---------------- single pipelined kernel ----------------
__global__ void __launch_bounds__(256, 6)
k_pipe(const float* __restrict__ pc, const float* __restrict__ logits,
       uint32_t k1a, uint32_t k1b, uint32_t k2a, uint32_t k2b,
       float* __restrict__ out, int has_mean) {
    const int bid = blockIdx.x;
    const int t   = threadIdx.x;
    const int lane = t & 31, warp = t >> 5;

    __shared__ union {
        struct {
            float ss[8][3];
            int   swarp[8], swpref[8], stot, islast;
        } m;
        int coarse[NCOARSE];                  // 2 KB (select path)
    } sh;

    if (bid < NMASKBLK) {
        // ======================= MASK PATH =======================
        const int b    = bid >> 6;            // NTILE = 64
        const int tile = bid & 63;

        const float*  l0 = logits + (size_t)b * 2 * NPTS;
        const float*  l1 = l0 + NPTS;
        const float4* p4 = (const float4*)pc + (size_t)b * NPTS;

        const int wbase = tile * TILE + warp * 256;
        float sx = 0.f, sy = 0.f, sz = 0.f;

        #pragma unroll
        for (int k = 0; k < 8; ++k) {
            const int n = wbase + k * 32 + lane;
            const bool m = __ldg(&l0[n]) < __ldg(&l1[n]);
            const unsigned bal = __ballot_sync(0xffffffffu, m);
            const float4 p = __ldg(&p4[n]);
            if (lane == 0)
                g_maskbits[(size_t)b * NWORDS + (unsigned)(wbase + k * 32) / 32] = bal;
            if (m) { sx += p.x; sy += p.y; sz += p.z; }
        }

        if (warp == 0) {                      // free ALU: threefry draws
            const uint32_t slot = (uint32_t)(b * MPTS + tile * 32 + lane);
            uint32_t h0, h1, q0, q1;
            threefry2x32(k1a, k1b, 0u, slot, h0, h1);
            threefry2x32(k2a, k2b, 0u, slot, q0, q1);
            g_rand[slot] = make_uint2(h0 ^ h1, q0 ^ q1);
        }

        #pragma unroll
        for (int o = 16; o; o >>= 1) {
            sx += __shfl_down_sync(0xffffffffu, sx, o);
            sy += __shfl_down_sync(0xffffffffu, sy, o);
            sz += __shfl_down_sync(0xffffffffu, sz, o);
        }
        if (lane == 0) { sh.m.ss[warp][0] = sx; sh.m.ss[warp][1] = sy; sh.m.ss[warp][2] = sz; }
        __syncthreads();
        if (warp == 0 && lane < 8) {
            sx = sh.m.ss[lane][0]; sy = sh.m.ss[lane][1]; sz = sh.m.ss[lane][2];
            #pragma unroll
            for (int o = 4; o; o >>= 1) {
                sx += __shfl_down_sync(0x000000ffu, sx, o);
                sy += __shfl_down_sync(0x000000ffu, sy, o);
                sz += __shfl_down_sync(0x000000ffu, sz, o);
            }
            if (lane == 0) {
                const int idx = b * NTILE + tile;
                g_blocksum[idx * 3 + 0] = sx;
                g_blocksum[idx * 3 + 1] = sy;
                g_blocksum[idx * 3 + 2] = sz;
            }
        }
        __syncthreads();

        // arrival protocol
        if (t == 0) {
            __threadfence();
            const int old = atomicAdd(&g_arrive[b], 1);
            sh.m.islast = (old == NTILE - 1);
        }
        __syncthreads();
        if (!sh.m.islast) return;
        if (t == 0) g_arrive[b] = 0;          // reset for next replay
        __threadfence();

        // ---- last block of batch b: prefixes + meancnt, then release ----
        const uint4* mb4 = (const uint4*)(g_maskbits + (size_t)b * NWORDS);
        uint4 w4[4];
        #pragma unroll
        for (int i = 0; i < 4; ++i) w4[i] = mb4[t * 4 + i];

        int s = 0;
        #pragma unroll
        for (int i = 0; i < 4; ++i)
            s += __popc(w4[i].x) + __popc(w4[i].y) + __popc(w4[i].z) + __popc(w4[i].w);

        int inc = s;
        #pragma unroll
        for (int o = 1; o < 32; o <<= 1) {
            int v = __shfl_up_sync(0xffffffffu, inc, o);
            if (lane >= o) inc += v;
        }
        if (lane == 31) sh.m.swarp[warp] = inc;
        __syncthreads();
        if (warp == 0 && lane < 8) {
            int v = sh.m.swarp[lane], winc = v;
            #pragma unroll
            for (int o = 1; o < 8; o <<= 1) {
                int u = __shfl_up_sync(0x000000ffu, winc, o);
                if (lane >= o) winc += u;
            }
            sh.m.swpref[lane] = winc - v;
            if (lane == 7) sh.m.stot = winc;
        }
        __syncthreads();

        {
            int run = sh.m.swpref[warp] + (inc - s);
            const int c0 = run;
            int* __restrict__ pref = g_wordpref + (size_t)b * NWORDS + t * 16;
            int tmp[4];
            #pragma unroll
            for (int i = 0; i < 2; ++i) {
                tmp[0] = run; run += __popc(w4[i].x);
                tmp[1] = run; run += __popc(w4[i].y);
                tmp[2] = run; run += __popc(w4[i].z);
                tmp[3] = run; run += __popc(w4[i].w);
                ((int4*)pref)[i] = make_int4(tmp[0], tmp[1], tmp[2], tmp[3]);
            }
            const int c1 = run;
            #pragma unroll
            for (int i = 2; i < 4; ++i) {
                tmp[0] = run; run += __popc(w4[i].x);
                tmp[1] = run; run += __popc(w4[i].y);
                tmp[2] = run; run += __popc(w4[i].z);
                tmp[3] = run; run += __popc(w4[i].w);
                ((int4*)pref)[i] = make_int4(tmp[0], tmp[1], tmp[2], tmp[3]);
            }
            ((int2*)(g_coarse + (size_t)b * NCOARSE))[t] = make_int2(c0, c1);
        }

        const int tot = sh.m.stot;
        if (warp == 0) {
            const int i0 = (b * NTILE + lane) * 3;
            const int i1 = (b * NTILE + lane + 32) * 3;
            float mx = g_blocksum[i0 + 0] + g_blocksum[i1 + 0];
            float my = g_blocksum[i0 + 1] + g_blocksum[i1 + 1];
            float mz = g_blocksum[i0 + 2] + g_blocksum[i1 + 2];
            #pragma unroll
            for (int o = 16; o; o >>= 1) {
                mx += __shfl_down_sync(0xffffffffu, mx, o);
                my += __shfl_down_sync(0xffffffffu, my, o);
                mz += __shfl_down_sync(0xffffffffu, mz, o);
            }
            if (lane == 0) {
                const float d = fmaxf((float)tot, 1.0f);
                mx /= d; my /= d; mz /= d;
                g_meancnt[b] = make_float4(mx, my, mz, __int_as_float(tot));
                if (has_mean) {
                    float* om = out + (size_t)BATCH * MPTS * 3;
                    om[b * 3 + 0] = mx; om[b * 3 + 1] = my; om[b * 3 + 2] = mz;
                }
            }
        }

        // release: publish, then set flag
        __threadfence();
        __syncthreads();
        if (t == 0) atomicExch(&g_ready[b], 1);
        return;
    }

    // ======================= SELECT PATH =======================
    const int sbid = bid - NMASKBLK;
    const int b    = sbid >> 3;               // 8 blocks per batch
    const int blk  = sbid & 7;
    const int j    = blk * 256 + t;           // 0..MPTS-1
    const int slot = b * MPTS + j;

    // acquire: spin until batch b is published
    if (t == 0) {
        while (atomicAdd(&g_ready[b], 0) == 0) __nanosleep(64);
    }
    __syncthreads();
    __threadfence();                          // acquire fence in every thread

    ((int2*)sh.coarse)[t] = __ldg(&((const int2*)(g_coarse + (size_t)b * NCOARSE))[t]);
    const float4 mc   = __ldg(&g_meancnt[b]);
    const uint2  rnd2 = __ldg(&g_rand[slot]);
    const int cnt = __float_as_int(mc.w);
    __syncthreads();

    float* __restrict__ o = out + (size_t)slot * 3;

    if (cnt == 0) {                           // empty-mask override: batch id
        const float v = (float)b;
        o[0] = v; o[1] = v; o[2] = v;
    } else {
        const uint32_t span = (uint32_t)cnt;
        uint32_t mult = 65536u % span;
        mult = (mult * mult) % span;          // uint32 wraparound — matches lax semantics
        const int rnd = (int)(((rnd2.x % span) * mult + (rnd2.y % span)) % span);
        const int sel = (cnt <= MPTS && j < cnt) ? j : rnd;

        int lo = 0, hi = NCOARSE;
        #pragma unroll
        for (int st = 0; st < 9; ++st) {      // 2^9 = 512
            const int mid = (lo + hi) >> 1;
            const bool le = (sh.coarse[mid] <= sel);
            lo = le ? mid : lo;
            hi = le ? hi  : mid;
        }

        const int4*  pf = (const int4*) (g_wordpref + (size_t)b * NWORDS + lo * 8);
        const uint4* wf = (const uint4*)(g_maskbits + (size_t)b * NWORDS + lo * 8);
        const int4  pA = __ldg(&pf[0]);
        const int4  pB = __ldg(&pf[1]);
        const uint4 wA = __ldg(&wf[0]);
        const uint4 wB = __ldg(&wf[1]);

        const int k = (pA.y <= sel) + (pA.z <= sel) + (pA.w <= sel)
                    + (pB.x <= sel) + (pB.y <= sel) + (pB.z <= sel) + (pB.w <= sel);
        int plo = pA.x;
        plo = (k >= 1) ? pA.y : plo;  plo = (k >= 2) ? pA.z : plo;
        plo = (k >= 3) ? pA.w : plo;  plo = (k >= 4) ? pB.x : plo;
        plo = (k >= 5) ? pB.y : plo;  plo = (k >= 6) ? pB.z : plo;
        plo = (k >= 7) ? pB.w : plo;
        unsigned w = wA.x;
        w = (k >= 1) ? wA.y : w;  w = (k >= 2) ? wA.z : w;
        w = (k >= 3) ? wA.w : w;  w = (k >= 4) ? wB.x : w;
        w = (k >= 5) ? wB.y : w;  w = (k >= 6) ? wB.z : w;
        w = (k >= 7) ? wB.w : w;
        const int word = lo * 8 + k;

        int r = sel - plo;
        int p = 0;
        {
            int cc = __popc(w & 0xFFFFu); if (r >= cc) { r -= cc; p += 16; w >>= 16; }
            cc = __popc(w & 0xFFu);       if (r >= cc) { r -= cc; p += 8;  w >>= 8;  }
            cc = __popc(w & 0xFu);        if (r >= cc) { r -= cc; p += 4;  w >>= 4;  }
            cc = __popc(w & 0x3u);        if (r >= cc) { r -= cc; p += 2;  w >>= 2;  }
            cc = (int)(w & 1u);           if (r >= cc) {          p += 1;            }
        }
        const int idx = word * 32 + p;

        const float4 pt = __ldg((const float4*)pc + (size_t)b * NPTS + idx);
        o[0] = pt.x - mc.x;
        o[1] = pt.y - mc.y;
        o[2] = pt.z - mc.z;
    }

    // flag reset for graph replay: 8th finishing select block of batch b
    __syncthreads();
    if (t == 0) {
        if (atomicAdd(&g_seldone[b], 1) == 7) {
            g_seldone[b] = 0;
            atomicExch(&g_ready[b], 0);
        }
    }
}

// ---------------- launch ----------------
extern "C" void kernel_launch(void* const* d_in, const int* in_sizes, int n_in,
                              void* d_out, int out_size) {
    const float* pc     = (const float*)d_in[0];
    const float* logits = (const float*)d_in[1];
    if (n_in >= 2 && in_sizes[0] == BATCH * 2 * NPTS && in_sizes[1] == BATCH * NPTS * 4) {
        pc     = (const float*)d_in[1];
        logits = (const float*)d_in[0];
    }
    float* out = (float*)d_out;

    // split(key(42)) — partitionable/foldlike: counters (0,0) and (0,1)
    uint32_t k1a, k1b, k2a, k2b;
    threefry2x32(0u, 42u, 0u, 0u, k1a, k1b);
    threefry2x32(0u, 42u, 0u, 1u, k2a, k2b);

    const size_t obj_elems = (size_t)BATCH * MPTS * 3;
    const int has_mean = (out_size >= (int)(obj_elems + BATCH * 3)) ? 1 : 0;

    k_pipe<<<NMASKBLK + NSELBLK, 256>>>(pc, logits, k1a, k1b, k2a, k2b, out, has_mean);
}